// round 9
// baseline (speedup 1.0000x reference)
#include <cuda_runtime.h>
#include <cuda_fp16.h>
#include <math.h>
#include <stdint.h>

// Problem constants
#define BB 2
#define SS 2048
#define DD 1024
#define HH 16
#define HD 64
#define BS (BB*SS)          // 4096 rows
#define D3 (3*DD)           // 3072

// ---------------- scratch (device globals; no allocation allowed) ------------
__device__ __half g_xnh [BS*DD];     // fp16 LN output
__device__ __half g_qkvh[BS*D3];     // fp16 post-rope q,k + v (A of in-proj)
__device__ __half g_atth[BS*DD];     // fp16 attention out
__device__ __half g_q_hi[BS*DD], g_q_lo[BS*DD];
__device__ __half g_k_hi[BS*DD], g_k_lo[BS*DD];
__device__ __half g_v_hi[BS*DD], g_v_lo[BS*DD];
__device__ __half g_wqkvh[D3*DD];
__device__ __half g_winh [D3*DD];
__device__ __half g_wouth[DD*DD];
__device__ float  g_cos[SS*(DD/2)];
__device__ float  g_sin[SS*(DD/2)];

// ---------------- ptx helpers -------------------------------------------------
__device__ __forceinline__ uint32_t smem_u32(const void* p) {
    uint32_t a;
    asm("{ .reg .u64 t; cvta.to.shared.u64 t, %1; cvt.u32.u64 %0, t; }"
        : "=r"(a) : "l"(p));
    return a;
}

__device__ __forceinline__ void cp16(uint32_t s, const void* g) {
    asm volatile("cp.async.cg.shared.global [%0], [%1], 16;" :: "r"(s), "l"(g));
}
__device__ __forceinline__ void cp_commit() {
    asm volatile("cp.async.commit_group;" ::: "memory");
}
template <int N>
__device__ __forceinline__ void cp_wait() {
    asm volatile("cp.async.wait_group %0;" :: "n"(N) : "memory");
}

#define LDSM4(r, addr) \
    asm volatile("ldmatrix.sync.aligned.m8n8.x4.shared.b16 {%0,%1,%2,%3}, [%4];" \
        : "=r"((r)[0]), "=r"((r)[1]), "=r"((r)[2]), "=r"((r)[3]) : "r"(addr))
#define LDSM2(r, addr) \
    asm volatile("ldmatrix.sync.aligned.m8n8.x2.shared.b16 {%0,%1}, [%2];" \
        : "=r"((r)[0]), "=r"((r)[1]) : "r"(addr))
#define LDSM2T(r, addr) \
    asm volatile("ldmatrix.sync.aligned.m8n8.x2.trans.shared.b16 {%0,%1}, [%2];" \
        : "=r"((r)[0]), "=r"((r)[1]) : "r"(addr))

__device__ __forceinline__ void mma_fp16(float (&d)[4],
                                         const uint32_t (&a)[4],
                                         const uint32_t (&b)[2]) {
    asm volatile(
        "mma.sync.aligned.m16n8k16.row.col.f32.f16.f16.f32 "
        "{%0,%1,%2,%3}, {%4,%5,%6,%7}, {%8,%9}, {%0,%1,%2,%3};"
        : "+f"(d[0]), "+f"(d[1]), "+f"(d[2]), "+f"(d[3])
        : "r"(a[0]), "r"(a[1]), "r"(a[2]), "r"(a[3]),
          "r"(b[0]), "r"(b[1]));
}

__device__ __forceinline__ uint32_t pack_h2(float x, float y) {
    __half2 h;
    h.x = __float2half_rn(x);
    h.y = __float2half_rn(y);
    return *(uint32_t*)&h;
}

__device__ __forceinline__ void split2(float2 v, uint32_t& hi, uint32_t& lo) {
    __half hx = __float2half_rn(v.x);
    __half hy = __float2half_rn(v.y);
    __half lx = __float2half_rn(v.x - __half2float(hx));
    __half ly = __float2half_rn(v.y - __half2float(hy));
    __half2 h; h.x = hx; h.y = hy;
    __half2 l; l.x = lx; l.y = ly;
    hi = *(uint32_t*)&h;
    lo = *(uint32_t*)&l;
}

// ---------------- fused fp32 -> fp16 weight conversion ------------------------
__global__ void __launch_bounds__(256) f2h_all(const float* __restrict__ w1,
                                               const float* __restrict__ w2,
                                               const float* __restrict__ w3) {
    const int s1 = D3*DD/4, s2 = 2*(D3*DD/4), s3 = 2*(D3*DD/4) + DD*DD/4;
    int i = blockIdx.x * blockDim.x + threadIdx.x;
    if (i >= s3) return;
    const float* src;
    __half* dst;
    int j;
    if (i < s1)      { src = w1; dst = g_wqkvh; j = i; }
    else if (i < s2) { src = w2; dst = g_winh;  j = i - s1; }
    else             { src = w3; dst = g_wouth; j = i - s2; }
    float4 v = ((const float4*)src)[j];
    __half2 h0 = __floats2half2_rn(v.x, v.y);
    __half2 h1 = __floats2half2_rn(v.z, v.w);
    *(uint2*)(dst + (size_t)j * 4) = make_uint2(*(uint32_t*)&h0, *(uint32_t*)&h1);
}

// ---------------- LayerNorm -> fp16 -------------------------------------------
__global__ void __launch_bounds__(256) ln_kernel(const float* __restrict__ x,
                                                 const float* __restrict__ g,
                                                 const float* __restrict__ bta) {
    int row = blockIdx.x;
    const float4* xr = (const float4*)(x + (size_t)row * DD);
    int t = threadIdx.x;
    float4 v = xr[t];
    float s  = v.x + v.y + v.z + v.w;
    float sq = v.x*v.x + v.y*v.y + v.z*v.z + v.w*v.w;
    #pragma unroll
    for (int off = 16; off; off >>= 1) {
        s  += __shfl_xor_sync(0xffffffffu, s,  off);
        sq += __shfl_xor_sync(0xffffffffu, sq, off);
    }
    __shared__ float red[16];
    int warp = t >> 5, lane = t & 31;
    if (lane == 0) { red[warp] = s; red[8 + warp] = sq; }
    __syncthreads();
    float ts = 0.f, tsq = 0.f;
    #pragma unroll
    for (int w = 0; w < 8; w++) { ts += red[w]; tsq += red[8 + w]; }
    float mu  = ts * (1.0f / DD);
    float var = tsq * (1.0f / DD) - mu * mu;
    float rs  = rsqrtf(var + 1e-5f);
    int col = t * 4;
    float4 gg = *(const float4*)(g   + col);
    float4 bb = *(const float4*)(bta + col);
    __half2 h0 = __floats2half2_rn((v.x - mu) * rs * gg.x + bb.x,
                                   (v.y - mu) * rs * gg.y + bb.y);
    __half2 h1 = __floats2half2_rn((v.z - mu) * rs * gg.z + bb.z,
                                   (v.w - mu) * rs * gg.w + bb.w);
    *(uint2*)(g_xnh + (size_t)row * DD + col) = make_uint2(*(uint32_t*)&h0, *(uint32_t*)&h1);
}

// ---------------- RoPE tables -------------------------------------------------
__global__ void rope_table_kernel() {
    int idx = blockIdx.x * blockDim.x + threadIdx.x;
    if (idx >= SS * (DD/2)) return;
    int pos = idx >> 9;
    int i   = idx & 511;
    double invf = exp(-((double)(2 * i) / (double)DD) * log(10000.0));
    float  ang  = __fmul_rn((float)pos, (float)invf);
    double r    = (double)ang;
    const double TWO_PI = 6.283185307179586476925286766559;
    r -= TWO_PI * rint(r / TWO_PI);
    float rf = (float)r;
    g_cos[idx] = cosf(rf);
    g_sin[idx] = sinf(rf);
}

// ---------------- pipelined HGEMM core: BK=64, 3-stage cp.async ---------------
// Rolling 1-ahead register fragment prefetch hides LDSM->HMMA latency.
#define GH_ROWB   144                   // bytes per smem row (72 halfs: 64 + pad)
#define GH_TILE   (128 * GH_ROWB)       // 18432 B per operand per stage
#define GH_STAGE  (2 * GH_TILE)         // 36864
#define GH_SMEM   (3 * GH_STAGE)        // 110592

struct GemmAcc { float a[4][4][4]; };

__device__ __forceinline__ void gemm_ld_stage(const __half* __restrict__ Ab, int lda,
                                              const __half* __restrict__ Bb, int ldb,
                                              uint32_t st, int k0, int tid) {
    #pragma unroll
    for (int i = 0; i < 8; i++) {
        int c   = tid + i * 256;          // 0..2047
        int op  = c >> 10;                // 0 = A, 1 = B
        int row = (c & 1023) >> 3;        // 0..127
        int ck  = (c & 7) * 8;            // halfs 0..56
        const __half* src = (op ? Bb + (size_t)row * ldb : Ab + (size_t)row * lda) + k0 + ck;
        cp16(st + (uint32_t)(op * GH_TILE + row * GH_ROWB + ck * 2), src);
    }
}

__device__ __forceinline__ void gemm_core(const __half* __restrict__ A,
                                          const __half* __restrict__ B,
                                          int K, int lda, int ldb,
                                          int mblk, int nblk,
                                          uint32_t sbase, GemmAcc& AC) {
    int tid = threadIdx.x, warp = tid >> 5, lane = tid & 31;
    int wm = (warp & 1) * 64;
    int wn = (warp >> 1) * 32;

    const __half* Ab = A + (size_t)(mblk * 128) * lda;
    const __half* Bb = B + (size_t)(nblk * 128) * ldb;

    uint32_t aOff[4], bOff[4];
    #pragma unroll
    for (int mt = 0; mt < 4; mt++)
        aOff[mt] = (uint32_t)((wm + mt * 16 + (lane & 15)) * GH_ROWB + (lane >> 4) * 16);
    #pragma unroll
    for (int nt = 0; nt < 4; nt++)
        bOff[nt] = (uint32_t)((wn + nt * 8 + (lane & 7)) * GH_ROWB + ((lane >> 3) & 1) * 16)
                 + GH_TILE;

    #pragma unroll
    for (int mt = 0; mt < 4; mt++)
        #pragma unroll
        for (int nt = 0; nt < 4; nt++)
            #pragma unroll
            for (int r = 0; r < 4; r++) AC.a[mt][nt][r] = 0.f;

    int nk = K >> 6;

    // prologue: stages 0,1
    gemm_ld_stage(Ab, lda, Bb, ldb, sbase, 0, tid);
    cp_commit();
    gemm_ld_stage(Ab, lda, Bb, ldb, sbase + GH_STAGE, 64, tid);
    cp_commit();
    cp_wait<1>();          // stage 0 ready
    __syncthreads();

    for (int it = 0; it < nk; it++) {
        // prefetch stage it+2 (slot freed by sync at end of it-1)
        if (it + 2 < nk) {
            int s = it + 2;
            gemm_ld_stage(Ab, lda, Bb, ldb,
                          sbase + (uint32_t)((s % 3) * GH_STAGE), s << 6, tid);
        }
        cp_commit();

        uint32_t sa = sbase + (uint32_t)((it % 3) * GH_STAGE);

        // rolling 1-ahead fragment pipeline over 4 ks steps
        uint32_t af[2][4][4], bf[2][4][2];
        #pragma unroll
        for (int mt = 0; mt < 4; mt++) LDSM4(af[0][mt], sa + aOff[mt]);
        #pragma unroll
        for (int nt = 0; nt < 4; nt++) LDSM2(bf[0][nt], sa + bOff[nt]);

        #pragma unroll
        for (int ks = 0; ks < 4; ks++) {
            int cur = ks & 1, nxt = cur ^ 1;
            if (ks < 3) {
                #pragma unroll
                for (int mt = 0; mt < 4; mt++) LDSM4(af[nxt][mt], sa + aOff[mt] + (ks + 1) * 32);
                #pragma unroll
                for (int nt = 0; nt < 4; nt++) LDSM2(bf[nxt][nt], sa + bOff[nt] + (ks + 1) * 32);
            }
            #pragma unroll
            for (int mt = 0; mt < 4; mt++)
                #pragma unroll
                for (int nt = 0; nt < 4; nt++)
                    mma_fp16(AC.a[mt][nt], af[cur][mt], bf[cur][nt]);
        }

        if (it + 1 < nk) {
            cp_wait<1>();      // ensure stage it+1 ready (it+2 may be in flight)
            __syncthreads();
        }
    }
}

// ---- QKV GEMM with fused bias + RoPE epilogue -> fp16 g_qkvh -----------------
__global__ void __launch_bounds__(256, 2)
gemm_qkv_rope(const float* __restrict__ bias) {
    extern __shared__ __align__(16) char gsm[];
    GemmAcc AC;
    gemm_core(g_xnh, g_wqkvh, DD, DD, DD, blockIdx.y, blockIdx.x, smem_u32(gsm), AC);
    int tid = threadIdx.x, warp = tid >> 5, lane = tid & 31;
    int g = lane >> 2, t4 = lane & 3;
    int wm = (warp & 1) * 64, wn = (warp >> 1) * 32;
    int sec = blockIdx.x >> 3;          // 0=q, 1=k, 2=v
    #pragma unroll
    for (int mt = 0; mt < 4; mt++) {
        int row = blockIdx.y * 128 + wm + mt * 16 + g;
        #pragma unroll
        for (int nt = 0; nt < 4; nt++) {
            int col = blockIdx.x * 128 + wn + nt * 8 + 2 * t4;
            float b0 = bias[col], b1 = bias[col + 1];
            float o0 = AC.a[mt][nt][0] + b0, o1 = AC.a[mt][nt][1] + b1;
            float o2 = AC.a[mt][nt][2] + b0, o3 = AC.a[mt][nt][3] + b1;
            if (sec < 2) {
                int i  = (col & 1023) >> 1;
                int p0 = row & (SS - 1);
                int p1 = (row + 8) & (SS - 1);
                float c0 = g_cos[p0 * 512 + i], s0 = g_sin[p0 * 512 + i];
                float c1 = g_cos[p1 * 512 + i], s1 = g_sin[p1 * 512 + i];
                float r0 = o0 * c0 - o1 * s0, r1 = o1 * c0 + o0 * s0;
                float r2 = o2 * c1 - o3 * s1, r3 = o3 * c1 + o2 * s1;
                o0 = r0; o1 = r1; o2 = r2; o3 = r3;
            }
            *(uint32_t*)&g_qkvh[(size_t)row * D3 + col]       = pack_h2(o0, o1);
            *(uint32_t*)&g_qkvh[(size_t)(row + 8) * D3 + col] = pack_h2(o2, o3);
        }
    }
}

// ---- merged in-projections (q,k,v) with hi/lo split epilogue -----------------
__global__ void __launch_bounds__(256, 2)
gemm_inproj(const float* __restrict__ bias_all) {
    extern __shared__ __align__(16) char gsm[];
    int sec = blockIdx.x >> 3, nb = blockIdx.x & 7;
    const __half* A = g_qkvh + sec * DD;
    const __half* B = g_winh + (size_t)sec * DD * DD;
    GemmAcc AC;
    gemm_core(A, B, DD, D3, DD, blockIdx.y, nb, smem_u32(gsm), AC);
    const float* bias = bias_all + sec * DD;
    __half *Chi, *Clo;
    if (sec == 0)      { Chi = g_q_hi; Clo = g_q_lo; }
    else if (sec == 1) { Chi = g_k_hi; Clo = g_k_lo; }
    else               { Chi = g_v_hi; Clo = g_v_lo; }
    int tid = threadIdx.x, warp = tid >> 5, lane = tid & 31;
    int g = lane >> 2, t4 = lane & 3;
    int wm = (warp & 1) * 64, wn = (warp >> 1) * 32;
    #pragma unroll
    for (int mt = 0; mt < 4; mt++) {
        int row = blockIdx.y * 128 + wm + mt * 16 + g;
        #pragma unroll
        for (int nt = 0; nt < 4; nt++) {
            int col = nb * 128 + wn + nt * 8 + 2 * t4;
            float b0 = bias[col], b1 = bias[col + 1];
            uint32_t hi, lo;
            split2(make_float2(AC.a[mt][nt][0] + b0, AC.a[mt][nt][1] + b1), hi, lo);
            *(uint32_t*)&Chi[(size_t)row * DD + col] = hi;
            *(uint32_t*)&Clo[(size_t)row * DD + col] = lo;
            split2(make_float2(AC.a[mt][nt][2] + b0, AC.a[mt][nt][3] + b1), hi, lo);
            *(uint32_t*)&Chi[(size_t)(row + 8) * DD + col] = hi;
            *(uint32_t*)&Clo[(size_t)(row + 8) * DD + col] = lo;
        }
    }
}

// ---- out-projection: fp32 epilogue -------------------------------------------
__global__ void __launch_bounds__(256, 2)
gemm_out(const float* __restrict__ bias, float* __restrict__ C) {
    extern __shared__ __align__(16) char gsm[];
    GemmAcc AC;
    gemm_core(g_atth, g_wouth, DD, DD, DD, blockIdx.y, blockIdx.x, smem_u32(gsm), AC);
    int tid = threadIdx.x, warp = tid >> 5, lane = tid & 31;
    int g = lane >> 2, t4 = lane & 3;
    int wm = (warp & 1) * 64, wn = (warp >> 1) * 32;
    #pragma unroll
    for (int mt = 0; mt < 4; mt++) {
        int row = blockIdx.y * 128 + wm + mt * 16 + g;
        #pragma unroll
        for (int nt = 0; nt < 4; nt++) {
            int col = blockIdx.x * 128 + wn + nt * 8 + 2 * t4;
            float b0 = bias[col], b1 = bias[col + 1];
            float2 o0 = make_float2(AC.a[mt][nt][0] + b0, AC.a[mt][nt][1] + b1);
            float2 o1 = make_float2(AC.a[mt][nt][2] + b0, AC.a[mt][nt][3] + b1);
            *(float2*)&C[(size_t)row * DD + col]       = o0;
            *(float2*)&C[(size_t)(row + 8) * DD + col] = o1;
        }
    }
}

// ---------------- Tensor-core flash attention (cp.async KV pipeline) ----------
#define AROW   72
#define AQ_HI  0
#define AQ_LO  (128*AROW)
#define AKV0   (2*128*AROW)
#define AKV_ST (4*64*AROW)
#define K_HI_O 0
#define K_LO_O (64*AROW)
#define V_HI_O (2*64*AROW)
#define V_LO_O (3*64*AROW)
#define ATT_SMEM ((AKV0 + 2*AKV_ST) * 2)   // 110592 bytes

__global__ void __launch_bounds__(256, 2) attn_kernel(const float* __restrict__ mask) {
    extern __shared__ __align__(16) __half asm_[];
    uint32_t sb = smem_u32(asm_);
    int q0 = blockIdx.x * 128;
    int h  = blockIdx.y;
    int b  = blockIdx.z;
    int tid = threadIdx.x, warp = tid >> 5, lane = tid & 31;
    int g = lane >> 2, t4 = lane & 3;

    const __half* qhig = g_q_hi + ((size_t)(b * SS + q0)) * DD + h * HD;
    const __half* qlog = g_q_lo + ((size_t)(b * SS + q0)) * DD + h * HD;
    const __half* khig = g_k_hi + ((size_t)b * SS) * DD + h * HD;
    const __half* klog = g_k_lo + ((size_t)b * SS) * DD + h * HD;
    const __half* vhig = g_v_hi + ((size_t)b * SS) * DD + h * HD;
    const __half* vlog = g_v_lo + ((size_t)b * SS) * DD + h * HD;
    const float* mrow0 = mask + ((size_t)(b * SS + q0 + warp * 16 + g)) * SS;
    const float* mrow1 = mrow0 + 8 * SS;

    {
        #pragma unroll
        for (int i = 0; i < 4; i++) {
            int c = tid + i * 256;
            int row = c >> 3, ck = (c & 7) * 8;
            cp16(sb + (uint32_t)(AQ_HI + row * AROW + ck) * 2, qhig + (size_t)row * DD + ck);
            cp16(sb + (uint32_t)(AQ_LO + row * AROW + ck) * 2, qlog + (size_t)row * DD + ck);
        }
        cp_commit();
    }
    {
        #pragma unroll
        for (int i = 0; i < 2; i++) {
            int c = tid + i * 256;
            int row = c >> 3, ck = (c & 7) * 8;
            uint32_t so = (uint32_t)(AKV0 + row * AROW + ck) * 2;
            cp16(sb + so + K_HI_O * 2, khig + (size_t)row * DD + ck);
            cp16(sb + so + K_LO_O * 2, klog + (size_t)row * DD + ck);
            cp16(sb + so + V_HI_O * 2, vhig + (size_t)row * DD + ck);
            cp16(sb + so + V_LO_O * 2, vlog + (size_t)row * DD + ck);
        }
        cp_commit();
    }

    cp_wait<0>();
    __syncthreads();

    uint32_t qhi[4][4];
    uint32_t qbase = sb + (uint32_t)((warp * 16 + (lane & 15)) * AROW * 2 + (lane >> 4) * 16);
    #pragma unroll
    for (int ks = 0; ks < 4; ks++) LDSM4(qhi[ks], qbase + ks * 32);

    float m0 = -1e30f, m1 = -1e30f, l0 = 0.f, l1 = 0.f;
    float oacc[8][4];
    #pragma unroll
    for (int nt = 0; nt < 8; nt++)
        #pragma unroll
        for (int r = 0; r < 4; r++) oacc[nt][r] = 0.f;

    for (int it = 0; it < SS / 64; it++) {
        if (it + 1 < SS / 64) {
            int j1 = (it + 1) * 64;
            uint32_t st = (uint32_t)(AKV0 + ((it + 1) & 1) * AKV_ST);
            #pragma unroll
            for (int i = 0; i < 2; i++) {
                int c = tid + i * 256;
                int row = c >> 3, ck = (c & 7) * 8;
                uint32_t so = (st + (uint32_t)(row * AROW + ck)) * 2;
                cp16(sb + so + K_HI_O * 2, khig + (size_t)(j1 + row) * DD + ck);
                cp16(sb + so + K_LO_O * 2, klog + (size_t)(j1 + row) * DD + ck);
                cp16(sb + so + V_HI_O * 2, vhig + (size_t)(j1 + row) * DD + ck);
                cp16(sb + so + V_LO_O * 2, vlog + (size_t)(j1 + row) * DD + ck);
            }
            cp_commit();
        }

        int j0 = it * 64;
        uint32_t stb = sb + (uint32_t)(AKV0 + (it & 1) * AKV_ST) * 2;
        uint32_t kfb = stb + (uint32_t)((lane & 7) * AROW * 2 + ((lane >> 3) & 1) * 16);
        uint32_t vfb = stb + V_HI_O * 2 + (uint32_t)((lane & 15) * AROW * 2);

        float sacc[8][4];
        #pragma unroll
        for (int nt = 0; nt < 8; nt++)
            #pragma unroll
            for (int r = 0; r < 4; r++) sacc[nt][r] = 0.f;

        #pragma unroll
        for (int ks = 0; ks < 4; ks++) {
            uint32_t qlo[4];
            LDSM4(qlo, qbase + AQ_LO * 2 + ks * 32);
            #pragma unroll
            for (int nt = 0; nt < 8; nt++) {
                uint32_t khi[2], klo[2];
                uint32_t ka = kfb + (uint32_t)(nt * 8 * AROW * 2) + ks * 32;
                LDSM2(khi, ka);
                LDSM2(klo, ka + K_LO_O * 2);
                mma_fp16(sacc[nt], qhi[ks], khi);
                mma_fp16(sacc[nt], qlo,     khi);
                mma_fp16(sacc[nt], qhi[ks], klo);
            }
        }

        const float scl = 0.125f;
        #pragma unroll
        for (int nt = 0; nt < 8; nt++) {
            int col = j0 + nt * 8 + 2 * t4;
            float2 mk0 = *(const float2*)&mrow0[col];
            float2 mk1 = *(const float2*)&mrow1[col];
            sacc[nt][0] = sacc[nt][0] * scl + mk0.x;
            sacc[nt][1] = sacc[nt][1] * scl + mk0.y;
            sacc[nt][2] = sacc[nt][2] * scl + mk1.x;
            sacc[nt][3] = sacc[nt][3] * scl + mk1.y;
        }

        float rx0 = -1e30f, rx1 = -1e30f;
        #pragma unroll
        for (int nt = 0; nt < 8; nt++) {
            rx0 = fmaxf(rx0, fmaxf(sacc[nt][0], sacc[nt][1]));
            rx1 = fmaxf(rx1, fmaxf(sacc[nt][2], sacc[nt][3]));
        }
        rx0 = fmaxf(rx0, __shfl_xor_sync(0xffffffffu, rx0, 1));
        rx0 = fmaxf(rx0, __shfl_xor_sync(0xffffffffu, rx0, 2));
        rx1 = fmaxf(rx1, __shfl_xor_sync(0xffffffffu, rx1, 1));
        rx1 = fmaxf(rx1, __shfl_xor_sync(0xffffffffu, rx1, 2));
        float mn0 = fmaxf(m0, rx0), mn1 = fmaxf(m1, rx1);
        float rs0 = 0.f, rs1 = 0.f;
        #pragma unroll
        for (int nt = 0; nt < 8; nt++) {
            sacc[nt][0] = __expf(sacc[nt][0] - mn0);
            sacc[nt][1] = __expf(sacc[nt][1] - mn0);
            sacc[nt][2] = __expf(sacc[nt][2] - mn1);
            sacc[nt][3] = __expf(sacc[nt][3] - mn1);
            rs0 += sacc[nt][0] + sacc[nt][1];
            rs1 += sacc[nt][2] + sacc[nt][3];
        }
        rs0 += __shfl_xor_sync(0xffffffffu, rs0, 1);
        rs0 += __shfl_xor_sync(0xffffffffu, rs0, 2);
        rs1 += __shfl_xor_sync(0xffffffffu, rs1, 1);
        rs1 += __shfl_xor_sync(0xffffffffu, rs1, 2);
        float c0 = __expf(m0 - mn0), c1 = __expf(m1 - mn1);
        l0 = l0 * c0 + rs0;  m0 = mn0;
        l1 = l1 * c1 + rs1;  m1 = mn1;
        #pragma unroll
        for (int nt = 0; nt < 8; nt++) {
            oacc[nt][0] *= c0; oacc[nt][1] *= c0;
            oacc[nt][2] *= c1; oacc[nt][3] *= c1;
        }

        #pragma unroll
        for (int kk = 0; kk < 4; kk++) {
            uint32_t pa[4];
            pa[0] = pack_h2(sacc[2*kk  ][0], sacc[2*kk  ][1]);
            pa[1] = pack_h2(sacc[2*kk  ][2], sacc[2*kk  ][3]);
            pa[2] = pack_h2(sacc[2*kk+1][0], sacc[2*kk+1][1]);
            pa[3] = pack_h2(sacc[2*kk+1][2], sacc[2*kk+1][3]);
            #pragma unroll
            for (int nt = 0; nt < 8; nt++) {
                uint32_t vhi[2], vlo[2];
                uint32_t va = vfb + (uint32_t)(kk * 16 * AROW * 2) + nt * 16;
                LDSM2T(vhi, va);
                LDSM2T(vlo, va + (V_LO_O - V_HI_O) * 2);
                mma_fp16(oacc[nt], pa, vhi);
                mma_fp16(oacc[nt], pa, vlo);
            }
        }

        if (it + 1 < SS / 64) {
            cp_wait<0>();
            __syncthreads();
        }
    }

    float inv0 = 1.0f / l0, inv1 = 1.0f / l1;
    __half* ob = g_atth + ((size_t)(b * SS + q0 + warp * 16)) * DD + h * HD;
    #pragma unroll
    for (int nt = 0; nt < 8; nt++) {
        int col = nt * 8 + 2 * t4;
        __half2 h0 = __floats2half2_rn(oacc[nt][0] * inv0, oacc[nt][1] * inv0);
        __half2 h1 = __floats2half2_rn(oacc[nt][2] * inv1, oacc[nt][3] * inv1);
        *(uint32_t*)&ob[(size_t)g * DD + col]       = *(uint32_t*)&h0;
        *(uint32_t*)&ob[(size_t)(g + 8) * DD + col] = *(uint32_t*)&h1;
    }
}

// ---------------- launch ------------------------------------------------------
extern "C" void kernel_launch(void* const* d_in, const int* in_sizes, int n_in,
                              void* d_out, int out_size) {
    const float* x     = (const float*)d_in[0];
    const float* mask  = (const float*)d_in[1];
    const float* ln_g  = (const float*)d_in[2];
    const float* ln_b  = (const float*)d_in[3];
    const float* w_qkv = (const float*)d_in[4];
    const float* b_qkv = (const float*)d_in[5];
    const float* in_w  = (const float*)d_in[6];
    const float* in_b  = (const float*)d_in[7];
    const float* out_w = (const float*)d_in[8];
    const float* out_b = (const float*)d_in[9];

    cudaFuncSetAttribute(attn_kernel,
                         cudaFuncAttributeMaxDynamicSharedMemorySize, ATT_SMEM);
    cudaFuncSetAttribute(gemm_qkv_rope,
                         cudaFuncAttributeMaxDynamicSharedMemorySize, GH_SMEM);
    cudaFuncSetAttribute(gemm_inproj,
                         cudaFuncAttributeMaxDynamicSharedMemorySize, GH_SMEM);
    cudaFuncSetAttribute(gemm_out,
                         cudaFuncAttributeMaxDynamicSharedMemorySize, GH_SMEM);

    // 0. fused weight conversions (fp32 -> fp16)
    int n4tot = 2 * (D3*DD/4) + DD*DD/4;
    f2h_all<<<(n4tot + 255)/256, 256>>>(w_qkv, in_w, out_w);
    // 1. LayerNorm -> fp16
    ln_kernel<<<BS, 256>>>(x, ln_g, ln_b);
    // 2. RoPE tables (consumed by the QKV epilogue)
    rope_table_kernel<<<(SS * (DD/2) + 255) / 256, 256>>>();
    // 3. fused QKV projection + bias + RoPE -> fp16 g_qkvh
    gemm_qkv_rope<<<dim3(D3/128, BS/128), 256, GH_SMEM>>>(b_qkv);
    // 4. merged in-projections -> hi/lo fp16
    gemm_inproj<<<dim3(D3/128, BS/128), 256, GH_SMEM>>>(in_b);
    // 5. tensor-core flash attention -> fp16
    attn_kernel<<<dim3(SS/128, HH, BB), 256, ATT_SMEM>>>(mask);
    // 6. out-projection -> d_out (fp32)
    gemm_out<<<dim3(DD/128, BS/128), 256, GH_SMEM>>>(out_b, (float*)d_out);
}

// round 10
// speedup vs baseline: 1.1495x; 1.1495x over previous
#include <cuda_runtime.h>
#include <cuda_fp16.h>
#include <math.h>
#include <stdint.h>

// Problem constants
#define BB 2
#define SS 2048
#define DD 1024
#define HH 16
#define HD 64
#define BS (BB*SS)          // 4096 rows
#define D3 (3*DD)           // 3072

// ---------------- scratch (device globals; no allocation allowed) ------------
__device__ __half g_xnh [BS*DD];     // fp16 LN output
__device__ __half g_qkvh[BS*D3];     // fp16 post-rope q,k + v (A of in-proj)
__device__ __half g_atth[BS*DD];     // fp16 attention out
__device__ __half g_q_hi[BS*DD];
__device__ __half g_k_hi[BS*DD], g_k_lo[BS*DD];
__device__ __half g_v_hi[BS*DD];
__device__ __half g_wqkvh[D3*DD];
__device__ __half g_winh [D3*DD];
__device__ __half g_wouth[DD*DD];
__device__ float  g_cos[SS*(DD/2)];
__device__ float  g_sin[SS*(DD/2)];

// ---------------- ptx helpers -------------------------------------------------
__device__ __forceinline__ uint32_t smem_u32(const void* p) {
    uint32_t a;
    asm("{ .reg .u64 t; cvta.to.shared.u64 t, %1; cvt.u32.u64 %0, t; }"
        : "=r"(a) : "l"(p));
    return a;
}

__device__ __forceinline__ void cp16(uint32_t s, const void* g) {
    asm volatile("cp.async.cg.shared.global [%0], [%1], 16;" :: "r"(s), "l"(g));
}
__device__ __forceinline__ void cp_commit() {
    asm volatile("cp.async.commit_group;" ::: "memory");
}
template <int N>
__device__ __forceinline__ void cp_wait() {
    asm volatile("cp.async.wait_group %0;" :: "n"(N) : "memory");
}

#define LDSM4(r, addr) \
    asm volatile("ldmatrix.sync.aligned.m8n8.x4.shared.b16 {%0,%1,%2,%3}, [%4];" \
        : "=r"((r)[0]), "=r"((r)[1]), "=r"((r)[2]), "=r"((r)[3]) : "r"(addr))
#define LDSM2(r, addr) \
    asm volatile("ldmatrix.sync.aligned.m8n8.x2.shared.b16 {%0,%1}, [%2];" \
        : "=r"((r)[0]), "=r"((r)[1]) : "r"(addr))
#define LDSM2T(r, addr) \
    asm volatile("ldmatrix.sync.aligned.m8n8.x2.trans.shared.b16 {%0,%1}, [%2];" \
        : "=r"((r)[0]), "=r"((r)[1]) : "r"(addr))

__device__ __forceinline__ void mma_fp16(float (&d)[4],
                                         const uint32_t (&a)[4],
                                         const uint32_t (&b)[2]) {
    asm volatile(
        "mma.sync.aligned.m16n8k16.row.col.f32.f16.f16.f32 "
        "{%0,%1,%2,%3}, {%4,%5,%6,%7}, {%8,%9}, {%0,%1,%2,%3};"
        : "+f"(d[0]), "+f"(d[1]), "+f"(d[2]), "+f"(d[3])
        : "r"(a[0]), "r"(a[1]), "r"(a[2]), "r"(a[3]),
          "r"(b[0]), "r"(b[1]));
}

__device__ __forceinline__ uint32_t pack_h2(float x, float y) {
    __half2 h;
    h.x = __float2half_rn(x);
    h.y = __float2half_rn(y);
    return *(uint32_t*)&h;
}

__device__ __forceinline__ void split2(float2 v, uint32_t& hi, uint32_t& lo) {
    __half hx = __float2half_rn(v.x);
    __half hy = __float2half_rn(v.y);
    __half lx = __float2half_rn(v.x - __half2float(hx));
    __half ly = __float2half_rn(v.y - __half2float(hy));
    __half2 h; h.x = hx; h.y = hy;
    __half2 l; l.x = lx; l.y = ly;
    hi = *(uint32_t*)&h;
    lo = *(uint32_t*)&l;
}

// ---------------- fused fp32 -> fp16 weight conversion ------------------------
__global__ void __launch_bounds__(256) f2h_all(const float* __restrict__ w1,
                                               const float* __restrict__ w2,
                                               const float* __restrict__ w3) {
    const int s1 = D3*DD/4, s2 = 2*(D3*DD/4), s3 = 2*(D3*DD/4) + DD*DD/4;
    int i = blockIdx.x * blockDim.x + threadIdx.x;
    if (i >= s3) return;
    const float* src;
    __half* dst;
    int j;
    if (i < s1)      { src = w1; dst = g_wqkvh; j = i; }
    else if (i < s2) { src = w2; dst = g_winh;  j = i - s1; }
    else             { src = w3; dst = g_wouth; j = i - s2; }
    float4 v = ((const float4*)src)[j];
    __half2 h0 = __floats2half2_rn(v.x, v.y);
    __half2 h1 = __floats2half2_rn(v.z, v.w);
    *(uint2*)(dst + (size_t)j * 4) = make_uint2(*(uint32_t*)&h0, *(uint32_t*)&h1);
}

// ---------------- LayerNorm -> fp16 -------------------------------------------
__global__ void __launch_bounds__(256) ln_kernel(const float* __restrict__ x,
                                                 const float* __restrict__ g,
                                                 const float* __restrict__ bta) {
    int row = blockIdx.x;
    const float4* xr = (const float4*)(x + (size_t)row * DD);
    int t = threadIdx.x;
    float4 v = xr[t];
    float s  = v.x + v.y + v.z + v.w;
    float sq = v.x*v.x + v.y*v.y + v.z*v.z + v.w*v.w;
    #pragma unroll
    for (int off = 16; off; off >>= 1) {
        s  += __shfl_xor_sync(0xffffffffu, s,  off);
        sq += __shfl_xor_sync(0xffffffffu, sq, off);
    }
    __shared__ float red[16];
    int warp = t >> 5, lane = t & 31;
    if (lane == 0) { red[warp] = s; red[8 + warp] = sq; }
    __syncthreads();
    float ts = 0.f, tsq = 0.f;
    #pragma unroll
    for (int w = 0; w < 8; w++) { ts += red[w]; tsq += red[8 + w]; }
    float mu  = ts * (1.0f / DD);
    float var = tsq * (1.0f / DD) - mu * mu;
    float rs  = rsqrtf(var + 1e-5f);
    int col = t * 4;
    float4 gg = *(const float4*)(g   + col);
    float4 bb = *(const float4*)(bta + col);
    __half2 h0 = __floats2half2_rn((v.x - mu) * rs * gg.x + bb.x,
                                   (v.y - mu) * rs * gg.y + bb.y);
    __half2 h1 = __floats2half2_rn((v.z - mu) * rs * gg.z + bb.z,
                                   (v.w - mu) * rs * gg.w + bb.w);
    *(uint2*)(g_xnh + (size_t)row * DD + col) = make_uint2(*(uint32_t*)&h0, *(uint32_t*)&h1);
}

// ---------------- RoPE tables -------------------------------------------------
__global__ void rope_table_kernel() {
    int idx = blockIdx.x * blockDim.x + threadIdx.x;
    if (idx >= SS * (DD/2)) return;
    int pos = idx >> 9;
    int i   = idx & 511;
    double invf = exp(-((double)(2 * i) / (double)DD) * log(10000.0));
    float  ang  = __fmul_rn((float)pos, (float)invf);
    double r    = (double)ang;
    const double TWO_PI = 6.283185307179586476925286766559;
    r -= TWO_PI * rint(r / TWO_PI);
    float rf = (float)r;
    g_cos[idx] = cosf(rf);
    g_sin[idx] = sinf(rf);
}

// ---------------- pipelined HGEMM core: BK=64, 2-stage cp.async (R8) ----------
#define GH_ROWB   144                   // bytes per smem row (72 halfs: 64 + pad)
#define GH_TILE   (128 * GH_ROWB)       // 18432 B per operand per stage
#define GH_STAGE  (2 * GH_TILE)         // 36864
#define GH_SMEM   (2 * GH_STAGE)        // 73728

struct GemmAcc { float a[4][4][4]; };

__device__ __forceinline__ void gemm_ld_stage(const __half* __restrict__ Ab, int lda,
                                              const __half* __restrict__ Bb, int ldb,
                                              uint32_t st, int k0, int tid) {
    #pragma unroll
    for (int i = 0; i < 8; i++) {
        int c   = tid + i * 256;          // 0..2047
        int op  = c >> 10;                // 0 = A, 1 = B
        int row = (c & 1023) >> 3;        // 0..127
        int ck  = (c & 7) * 8;            // halfs 0..56
        const __half* src = (op ? Bb + (size_t)row * ldb : Ab + (size_t)row * lda) + k0 + ck;
        cp16(st + (uint32_t)(op * GH_TILE + row * GH_ROWB + ck * 2), src);
    }
}

__device__ __forceinline__ void gemm_core(const __half* __restrict__ A,
                                          const __half* __restrict__ B,
                                          int K, int lda, int ldb,
                                          int mblk, int nblk,
                                          uint32_t sbase, GemmAcc& AC) {
    int tid = threadIdx.x, warp = tid >> 5, lane = tid & 31;
    int wm = (warp & 1) * 64;
    int wn = (warp >> 1) * 32;

    const __half* Ab = A + (size_t)(mblk * 128) * lda;
    const __half* Bb = B + (size_t)(nblk * 128) * ldb;

    uint32_t aOff[4], bOff[4];
    #pragma unroll
    for (int mt = 0; mt < 4; mt++)
        aOff[mt] = (uint32_t)((wm + mt * 16 + (lane & 15)) * GH_ROWB + (lane >> 4) * 16);
    #pragma unroll
    for (int nt = 0; nt < 4; nt++)
        bOff[nt] = (uint32_t)((wn + nt * 8 + (lane & 7)) * GH_ROWB + ((lane >> 3) & 1) * 16)
                 + GH_TILE;

    #pragma unroll
    for (int mt = 0; mt < 4; mt++)
        #pragma unroll
        for (int nt = 0; nt < 4; nt++)
            #pragma unroll
            for (int r = 0; r < 4; r++) AC.a[mt][nt][r] = 0.f;

    int nk = K >> 6;

    gemm_ld_stage(Ab, lda, Bb, ldb, sbase, 0, tid);
    cp_commit();
    cp_wait<0>();
    __syncthreads();

    for (int it = 0; it < nk; it++) {
        if (it + 1 < nk) {
            gemm_ld_stage(Ab, lda, Bb, ldb,
                          sbase + ((it + 1) & 1) * GH_STAGE, (it + 1) << 6, tid);
            cp_commit();
        }

        uint32_t sa = sbase + (it & 1) * GH_STAGE;
        #pragma unroll
        for (int ks = 0; ks < 4; ks++) {
            uint32_t af[4][4], bf[4][2];
            #pragma unroll
            for (int mt = 0; mt < 4; mt++) LDSM4(af[mt], sa + aOff[mt] + ks * 32);
            #pragma unroll
            for (int nt = 0; nt < 4; nt++) LDSM2(bf[nt], sa + bOff[nt] + ks * 32);
            #pragma unroll
            for (int mt = 0; mt < 4; mt++)
                #pragma unroll
                for (int nt = 0; nt < 4; nt++)
                    mma_fp16(AC.a[mt][nt], af[mt], bf[nt]);
        }

        if (it + 1 < nk) {
            cp_wait<0>();
            __syncthreads();
        }
    }
}

// ---- QKV GEMM with fused bias + RoPE epilogue -> fp16 g_qkvh -----------------
__global__ void __launch_bounds__(256, 2)
gemm_qkv_rope(const float* __restrict__ bias) {
    extern __shared__ __align__(16) char gsm[];
    GemmAcc AC;
    gemm_core(g_xnh, g_wqkvh, DD, DD, DD, blockIdx.y, blockIdx.x, smem_u32(gsm), AC);
    int tid = threadIdx.x, warp = tid >> 5, lane = tid & 31;
    int g = lane >> 2, t4 = lane & 3;
    int wm = (warp & 1) * 64, wn = (warp >> 1) * 32;
    int sec = blockIdx.x >> 3;          // 0=q, 1=k, 2=v
    #pragma unroll
    for (int mt = 0; mt < 4; mt++) {
        int row = blockIdx.y * 128 + wm + mt * 16 + g;
        #pragma unroll
        for (int nt = 0; nt < 4; nt++) {
            int col = blockIdx.x * 128 + wn + nt * 8 + 2 * t4;
            float b0 = bias[col], b1 = bias[col + 1];
            float o0 = AC.a[mt][nt][0] + b0, o1 = AC.a[mt][nt][1] + b1;
            float o2 = AC.a[mt][nt][2] + b0, o3 = AC.a[mt][nt][3] + b1;
            if (sec < 2) {
                int i  = (col & 1023) >> 1;
                int p0 = row & (SS - 1);
                int p1 = (row + 8) & (SS - 1);
                float c0 = g_cos[p0 * 512 + i], s0 = g_sin[p0 * 512 + i];
                float c1 = g_cos[p1 * 512 + i], s1 = g_sin[p1 * 512 + i];
                float r0 = o0 * c0 - o1 * s0, r1 = o1 * c0 + o0 * s0;
                float r2 = o2 * c1 - o3 * s1, r3 = o3 * c1 + o2 * s1;
                o0 = r0; o1 = r1; o2 = r2; o3 = r3;
            }
            *(uint32_t*)&g_qkvh[(size_t)row * D3 + col]       = pack_h2(o0, o1);
            *(uint32_t*)&g_qkvh[(size_t)(row + 8) * D3 + col] = pack_h2(o2, o3);
        }
    }
}

// ---- merged in-projections: q,v -> hi only; k -> hi/lo split -----------------
__global__ void __launch_bounds__(256, 2)
gemm_inproj(const float* __restrict__ bias_all) {
    extern __shared__ __align__(16) char gsm[];
    int sec = blockIdx.x >> 3, nb = blockIdx.x & 7;
    const __half* A = g_qkvh + sec * DD;
    const __half* B = g_winh + (size_t)sec * DD * DD;
    GemmAcc AC;
    gemm_core(A, B, DD, D3, DD, blockIdx.y, nb, smem_u32(gsm), AC);
    const float* bias = bias_all + sec * DD;
    __half* Chi = (sec == 0) ? g_q_hi : (sec == 1) ? g_k_hi : g_v_hi;
    int tid = threadIdx.x, warp = tid >> 5, lane = tid & 31;
    int g = lane >> 2, t4 = lane & 3;
    int wm = (warp & 1) * 64, wn = (warp >> 1) * 32;
    #pragma unroll
    for (int mt = 0; mt < 4; mt++) {
        int row = blockIdx.y * 128 + wm + mt * 16 + g;
        #pragma unroll
        for (int nt = 0; nt < 4; nt++) {
            int col = nb * 128 + wn + nt * 8 + 2 * t4;
            float b0 = bias[col], b1 = bias[col + 1];
            float e0 = AC.a[mt][nt][0] + b0, e1 = AC.a[mt][nt][1] + b1;
            float e2 = AC.a[mt][nt][2] + b0, e3 = AC.a[mt][nt][3] + b1;
            if (sec == 1) {
                uint32_t hi, lo;
                split2(make_float2(e0, e1), hi, lo);
                *(uint32_t*)&Chi[(size_t)row * DD + col]    = hi;
                *(uint32_t*)&g_k_lo[(size_t)row * DD + col] = lo;
                split2(make_float2(e2, e3), hi, lo);
                *(uint32_t*)&Chi[(size_t)(row + 8) * DD + col]    = hi;
                *(uint32_t*)&g_k_lo[(size_t)(row + 8) * DD + col] = lo;
            } else {
                *(uint32_t*)&Chi[(size_t)row * DD + col]       = pack_h2(e0, e1);
                *(uint32_t*)&Chi[(size_t)(row + 8) * DD + col] = pack_h2(e2, e3);
            }
        }
    }
}

// ---- out-projection: fp32 epilogue -------------------------------------------
__global__ void __launch_bounds__(256, 2)
gemm_out(const float* __restrict__ bias, float* __restrict__ C) {
    extern __shared__ __align__(16) char gsm[];
    GemmAcc AC;
    gemm_core(g_atth, g_wouth, DD, DD, DD, blockIdx.y, blockIdx.x, smem_u32(gsm), AC);
    int tid = threadIdx.x, warp = tid >> 5, lane = tid & 31;
    int g = lane >> 2, t4 = lane & 3;
    int wm = (warp & 1) * 64, wn = (warp >> 1) * 32;
    #pragma unroll
    for (int mt = 0; mt < 4; mt++) {
        int row = blockIdx.y * 128 + wm + mt * 16 + g;
        #pragma unroll
        for (int nt = 0; nt < 4; nt++) {
            int col = blockIdx.x * 128 + wn + nt * 8 + 2 * t4;
            float b0 = bias[col], b1 = bias[col + 1];
            float2 o0 = make_float2(AC.a[mt][nt][0] + b0, AC.a[mt][nt][1] + b1);
            float2 o1 = make_float2(AC.a[mt][nt][2] + b0, AC.a[mt][nt][3] + b1);
            *(float2*)&C[(size_t)row * DD + col]       = o0;
            *(float2*)&C[(size_t)(row + 8) * DD + col] = o1;
        }
    }
}

// ---------------- Tensor-core flash attention ---------------------------------
// S = Qhi*(Khi + Klo) ; fp32 softmax ; O = P*Vhi.   96 mma per KV-iter.
#define AROW   72
#define AQ_HI  0
#define AKV0   (128*AROW)                // 9216 halfs
#define AKV_ST (3*64*AROW)               // 13824 halfs per stage
#define K_LO_O (64*AROW)
#define V_HI_O (2*64*AROW)
#define ATT_SMEM ((AKV0 + 2*AKV_ST) * 2) // 73728 bytes

__global__ void __launch_bounds__(256, 2) attn_kernel(const float* __restrict__ mask) {
    extern __shared__ __align__(16) __half asm_[];
    uint32_t sb = smem_u32(asm_);
    int q0 = blockIdx.x * 128;
    int h  = blockIdx.y;
    int b  = blockIdx.z;
    int tid = threadIdx.x, warp = tid >> 5, lane = tid & 31;
    int g = lane >> 2, t4 = lane & 3;

    const __half* qhig = g_q_hi + ((size_t)(b * SS + q0)) * DD + h * HD;
    const __half* khig = g_k_hi + ((size_t)b * SS) * DD + h * HD;
    const __half* klog = g_k_lo + ((size_t)b * SS) * DD + h * HD;
    const __half* vhig = g_v_hi + ((size_t)b * SS) * DD + h * HD;
    const float* mrow0 = mask + ((size_t)(b * SS + q0 + warp * 16 + g)) * SS;
    const float* mrow1 = mrow0 + 8 * SS;

    // stage Q hi (128 x 64): 1024 chunks
    {
        #pragma unroll
        for (int i = 0; i < 4; i++) {
            int c = tid + i * 256;
            int row = c >> 3, ck = (c & 7) * 8;
            cp16(sb + (uint32_t)(AQ_HI + row * AROW + ck) * 2, qhig + (size_t)row * DD + ck);
        }
        cp_commit();
    }
    // prologue: KV tile 0 (khi, klo, vhi): 1536 chunks
    {
        #pragma unroll
        for (int i = 0; i < 6; i++) {
            int c = tid + i * 256;
            int mat = c >> 9, row = (c & 511) >> 3, ck = (c & 7) * 8;
            const __half* src = (mat == 0 ? khig : mat == 1 ? klog : vhig)
                              + (size_t)row * DD + ck;
            cp16(sb + (uint32_t)(AKV0 + mat * 64 * AROW + row * AROW + ck) * 2, src);
        }
        cp_commit();
    }

    cp_wait<0>();
    __syncthreads();

    uint32_t qhi[4][4];
    uint32_t qbase = sb + (uint32_t)((warp * 16 + (lane & 15)) * AROW * 2 + (lane >> 4) * 16);
    #pragma unroll
    for (int ks = 0; ks < 4; ks++) LDSM4(qhi[ks], qbase + ks * 32);

    float m0 = -1e30f, m1 = -1e30f, l0 = 0.f, l1 = 0.f;
    float oacc[8][4];
    #pragma unroll
    for (int nt = 0; nt < 8; nt++)
        #pragma unroll
        for (int r = 0; r < 4; r++) oacc[nt][r] = 0.f;

    for (int it = 0; it < SS / 64; it++) {
        if (it + 1 < SS / 64) {
            int j1 = (it + 1) * 64;
            uint32_t st = (uint32_t)(AKV0 + ((it + 1) & 1) * AKV_ST);
            #pragma unroll
            for (int i = 0; i < 6; i++) {
                int c = tid + i * 256;
                int mat = c >> 9, row = (c & 511) >> 3, ck = (c & 7) * 8;
                const __half* src = (mat == 0 ? khig : mat == 1 ? klog : vhig)
                                  + (size_t)(j1 + row) * DD + ck;
                cp16(sb + (st + (uint32_t)(mat * 64 * AROW + row * AROW + ck)) * 2, src);
            }
            cp_commit();
        }

        int j0 = it * 64;
        uint32_t stb = sb + (uint32_t)(AKV0 + (it & 1) * AKV_ST) * 2;
        uint32_t kfb = stb + (uint32_t)((lane & 7) * AROW * 2 + ((lane >> 3) & 1) * 16);
        uint32_t vfb = stb + V_HI_O * 2 + (uint32_t)((lane & 15) * AROW * 2);

        // S = Qhi * (Khi + Klo)
        float sacc[8][4];
        #pragma unroll
        for (int nt = 0; nt < 8; nt++)
            #pragma unroll
            for (int r = 0; r < 4; r++) sacc[nt][r] = 0.f;

        #pragma unroll
        for (int ks = 0; ks < 4; ks++) {
            #pragma unroll
            for (int nt = 0; nt < 8; nt++) {
                uint32_t khi[2], klo[2];
                uint32_t ka = kfb + (uint32_t)(nt * 8 * AROW * 2) + ks * 32;
                LDSM2(khi, ka);
                LDSM2(klo, ka + K_LO_O * 2);
                mma_fp16(sacc[nt], qhi[ks], khi);
                mma_fp16(sacc[nt], qhi[ks], klo);
            }
        }

        const float scl = 0.125f;
        #pragma unroll
        for (int nt = 0; nt < 8; nt++) {
            int col = j0 + nt * 8 + 2 * t4;
            float2 mk0 = *(const float2*)&mrow0[col];
            float2 mk1 = *(const float2*)&mrow1[col];
            sacc[nt][0] = sacc[nt][0] * scl + mk0.x;
            sacc[nt][1] = sacc[nt][1] * scl + mk0.y;
            sacc[nt][2] = sacc[nt][2] * scl + mk1.x;
            sacc[nt][3] = sacc[nt][3] * scl + mk1.y;
        }

        float rx0 = -1e30f, rx1 = -1e30f;
        #pragma unroll
        for (int nt = 0; nt < 8; nt++) {
            rx0 = fmaxf(rx0, fmaxf(sacc[nt][0], sacc[nt][1]));
            rx1 = fmaxf(rx1, fmaxf(sacc[nt][2], sacc[nt][3]));
        }
        rx0 = fmaxf(rx0, __shfl_xor_sync(0xffffffffu, rx0, 1));
        rx0 = fmaxf(rx0, __shfl_xor_sync(0xffffffffu, rx0, 2));
        rx1 = fmaxf(rx1, __shfl_xor_sync(0xffffffffu, rx1, 1));
        rx1 = fmaxf(rx1, __shfl_xor_sync(0xffffffffu, rx1, 2));
        float mn0 = fmaxf(m0, rx0), mn1 = fmaxf(m1, rx1);
        float rs0 = 0.f, rs1 = 0.f;
        #pragma unroll
        for (int nt = 0; nt < 8; nt++) {
            sacc[nt][0] = __expf(sacc[nt][0] - mn0);
            sacc[nt][1] = __expf(sacc[nt][1] - mn0);
            sacc[nt][2] = __expf(sacc[nt][2] - mn1);
            sacc[nt][3] = __expf(sacc[nt][3] - mn1);
            rs0 += sacc[nt][0] + sacc[nt][1];
            rs1 += sacc[nt][2] + sacc[nt][3];
        }
        rs0 += __shfl_xor_sync(0xffffffffu, rs0, 1);
        rs0 += __shfl_xor_sync(0xffffffffu, rs0, 2);
        rs1 += __shfl_xor_sync(0xffffffffu, rs1, 1);
        rs1 += __shfl_xor_sync(0xffffffffu, rs1, 2);
        float c0 = __expf(m0 - mn0), c1 = __expf(m1 - mn1);
        l0 = l0 * c0 + rs0;  m0 = mn0;
        l1 = l1 * c1 + rs1;  m1 = mn1;
        #pragma unroll
        for (int nt = 0; nt < 8; nt++) {
            oacc[nt][0] *= c0; oacc[nt][1] *= c0;
            oacc[nt][2] *= c1; oacc[nt][3] *= c1;
        }

        // O += P * Vhi
        #pragma unroll
        for (int kk = 0; kk < 4; kk++) {
            uint32_t pa[4];
            pa[0] = pack_h2(sacc[2*kk  ][0], sacc[2*kk  ][1]);
            pa[1] = pack_h2(sacc[2*kk  ][2], sacc[2*kk  ][3]);
            pa[2] = pack_h2(sacc[2*kk+1][0], sacc[2*kk+1][1]);
            pa[3] = pack_h2(sacc[2*kk+1][2], sacc[2*kk+1][3]);
            #pragma unroll
            for (int nt = 0; nt < 8; nt++) {
                uint32_t vhi[2];
                LDSM2T(vhi, vfb + (uint32_t)(kk * 16 * AROW * 2) + nt * 16);
                mma_fp16(oacc[nt], pa, vhi);
            }
        }

        if (it + 1 < SS / 64) {
            cp_wait<0>();
            __syncthreads();
        }
    }

    float inv0 = 1.0f / l0, inv1 = 1.0f / l1;
    __half* ob = g_atth + ((size_t)(b * SS + q0 + warp * 16)) * DD + h * HD;
    #pragma unroll
    for (int nt = 0; nt < 8; nt++) {
        int col = nt * 8 + 2 * t4;
        __half2 h0 = __floats2half2_rn(oacc[nt][0] * inv0, oacc[nt][1] * inv0);
        __half2 h1 = __floats2half2_rn(oacc[nt][2] * inv1, oacc[nt][3] * inv1);
        *(uint32_t*)&ob[(size_t)g * DD + col]       = *(uint32_t*)&h0;
        *(uint32_t*)&ob[(size_t)(g + 8) * DD + col] = *(uint32_t*)&h1;
    }
}

// ---------------- launch ------------------------------------------------------
extern "C" void kernel_launch(void* const* d_in, const int* in_sizes, int n_in,
                              void* d_out, int out_size) {
    const float* x     = (const float*)d_in[0];
    const float* mask  = (const float*)d_in[1];
    const float* ln_g  = (const float*)d_in[2];
    const float* ln_b  = (const float*)d_in[3];
    const float* w_qkv = (const float*)d_in[4];
    const float* b_qkv = (const float*)d_in[5];
    const float* in_w  = (const float*)d_in[6];
    const float* in_b  = (const float*)d_in[7];
    const float* out_w = (const float*)d_in[8];
    const float* out_b = (const float*)d_in[9];

    cudaFuncSetAttribute(attn_kernel,
                         cudaFuncAttributeMaxDynamicSharedMemorySize, ATT_SMEM);
    cudaFuncSetAttribute(gemm_qkv_rope,
                         cudaFuncAttributeMaxDynamicSharedMemorySize, GH_SMEM);
    cudaFuncSetAttribute(gemm_inproj,
                         cudaFuncAttributeMaxDynamicSharedMemorySize, GH_SMEM);
    cudaFuncSetAttribute(gemm_out,
                         cudaFuncAttributeMaxDynamicSharedMemorySize, GH_SMEM);

    // 0. fused weight conversions (fp32 -> fp16)
    int n4tot = 2 * (D3*DD/4) + DD*DD/4;
    f2h_all<<<(n4tot + 255)/256, 256>>>(w_qkv, in_w, out_w);
    // 1. LayerNorm -> fp16
    ln_kernel<<<BS, 256>>>(x, ln_g, ln_b);
    // 2. RoPE tables (consumed by the QKV epilogue)
    rope_table_kernel<<<(SS * (DD/2) + 255) / 256, 256>>>();
    // 3. fused QKV projection + bias + RoPE -> fp16 g_qkvh
    gemm_qkv_rope<<<dim3(D3/128, BS/128), 256, GH_SMEM>>>(b_qkv);
    // 4. merged in-projections -> fp16 (k gets hi/lo)
    gemm_inproj<<<dim3(D3/128, BS/128), 256, GH_SMEM>>>(in_b);
    // 5. tensor-core flash attention -> fp16
    attn_kernel<<<dim3(SS/128, HH, BB), 256, ATT_SMEM>>>(mask);
    // 6. out-projection -> d_out (fp32)
    gemm_out<<<dim3(DD/128, BS/128), 256, GH_SMEM>>>(out_b, (float*)d_out);
}

// round 11
// speedup vs baseline: 1.2576x; 1.0941x over previous
#include <cuda_runtime.h>
#include <cuda_fp16.h>
#include <math.h>
#include <stdint.h>

// Problem constants
#define BB 2
#define SS 2048
#define DD 1024
#define HH 16
#define HD 64
#define BS (BB*SS)          // 4096 rows
#define D3 (3*DD)           // 3072

// ---------------- scratch (device globals; no allocation allowed) ------------
__device__ __half g_xnh [BS*DD];     // fp16 LN output
__device__ __half g_qkvh[BS*D3];     // fp16 post-rope q,k + v (A of in-proj)
__device__ __half g_atth[BS*DD];     // fp16 attention out
__device__ __half g_q_hi[BS*DD];
__device__ __half g_k_hi[BS*DD];
__device__ __half g_v_hi[BS*DD];
__device__ __half g_wqkvh[D3*DD];
__device__ __half g_winh [D3*DD];
__device__ __half g_wouth[DD*DD];
__device__ float  g_cos[SS*(DD/2)];
__device__ float  g_sin[SS*(DD/2)];

// ---------------- ptx helpers -------------------------------------------------
__device__ __forceinline__ uint32_t smem_u32(const void* p) {
    uint32_t a;
    asm("{ .reg .u64 t; cvta.to.shared.u64 t, %1; cvt.u32.u64 %0, t; }"
        : "=r"(a) : "l"(p));
    return a;
}

__device__ __forceinline__ void cp16(uint32_t s, const void* g) {
    asm volatile("cp.async.cg.shared.global [%0], [%1], 16;" :: "r"(s), "l"(g));
}
__device__ __forceinline__ void cp_commit() {
    asm volatile("cp.async.commit_group;" ::: "memory");
}
template <int N>
__device__ __forceinline__ void cp_wait() {
    asm volatile("cp.async.wait_group %0;" :: "n"(N) : "memory");
}

#define LDSM4(r, addr) \
    asm volatile("ldmatrix.sync.aligned.m8n8.x4.shared.b16 {%0,%1,%2,%3}, [%4];" \
        : "=r"((r)[0]), "=r"((r)[1]), "=r"((r)[2]), "=r"((r)[3]) : "r"(addr))
#define LDSM2(r, addr) \
    asm volatile("ldmatrix.sync.aligned.m8n8.x2.shared.b16 {%0,%1}, [%2];" \
        : "=r"((r)[0]), "=r"((r)[1]) : "r"(addr))
#define LDSM2T(r, addr) \
    asm volatile("ldmatrix.sync.aligned.m8n8.x2.trans.shared.b16 {%0,%1}, [%2];" \
        : "=r"((r)[0]), "=r"((r)[1]) : "r"(addr))

__device__ __forceinline__ void mma_fp16(float (&d)[4],
                                         const uint32_t (&a)[4],
                                         const uint32_t (&b)[2]) {
    asm volatile(
        "mma.sync.aligned.m16n8k16.row.col.f32.f16.f16.f32 "
        "{%0,%1,%2,%3}, {%4,%5,%6,%7}, {%8,%9}, {%0,%1,%2,%3};"
        : "+f"(d[0]), "+f"(d[1]), "+f"(d[2]), "+f"(d[3])
        : "r"(a[0]), "r"(a[1]), "r"(a[2]), "r"(a[3]),
          "r"(b[0]), "r"(b[1]));
}

__device__ __forceinline__ uint32_t pack_h2(float x, float y) {
    __half2 h;
    h.x = __float2half_rn(x);
    h.y = __float2half_rn(y);
    return *(uint32_t*)&h;
}

// ---------------- merged prep: weight f2h + LayerNorm + RoPE tables -----------
#define F2H_BLKS  7168       // 1835008 float4 chunks / 256
#define LN_BLKS   4096
#define RT_BLKS   4096       // 1048576 table entries / 256

__global__ void __launch_bounds__(256)
prep_kernel(const float* __restrict__ x,
            const float* __restrict__ lng, const float* __restrict__ lnb,
            const float* __restrict__ w1, const float* __restrict__ w2,
            const float* __restrict__ w3) {
    int bid = blockIdx.x;
    int t = threadIdx.x;
    if (bid < F2H_BLKS) {
        // weight conversion
        const int s1 = D3*DD/4, s2 = 2*(D3*DD/4), s3 = 2*(D3*DD/4) + DD*DD/4;
        int i = bid * 256 + t;
        if (i >= s3) return;
        const float* src;
        __half* dst;
        int j;
        if (i < s1)      { src = w1; dst = g_wqkvh; j = i; }
        else if (i < s2) { src = w2; dst = g_winh;  j = i - s1; }
        else             { src = w3; dst = g_wouth; j = i - s2; }
        float4 v = ((const float4*)src)[j];
        __half2 h0 = __floats2half2_rn(v.x, v.y);
        __half2 h1 = __floats2half2_rn(v.z, v.w);
        *(uint2*)(dst + (size_t)j * 4) = make_uint2(*(uint32_t*)&h0, *(uint32_t*)&h1);
    } else if (bid < F2H_BLKS + LN_BLKS) {
        // LayerNorm row
        int row = bid - F2H_BLKS;
        const float4* xr = (const float4*)(x + (size_t)row * DD);
        float4 v = xr[t];
        float s  = v.x + v.y + v.z + v.w;
        float sq = v.x*v.x + v.y*v.y + v.z*v.z + v.w*v.w;
        #pragma unroll
        for (int off = 16; off; off >>= 1) {
            s  += __shfl_xor_sync(0xffffffffu, s,  off);
            sq += __shfl_xor_sync(0xffffffffu, sq, off);
        }
        __shared__ float red[16];
        int warp = t >> 5, lane = t & 31;
        if (lane == 0) { red[warp] = s; red[8 + warp] = sq; }
        __syncthreads();
        float ts = 0.f, tsq = 0.f;
        #pragma unroll
        for (int w = 0; w < 8; w++) { ts += red[w]; tsq += red[8 + w]; }
        float mu  = ts * (1.0f / DD);
        float var = tsq * (1.0f / DD) - mu * mu;
        float rs  = rsqrtf(var + 1e-5f);
        int col = t * 4;
        float4 gg = *(const float4*)(lng + col);
        float4 bb = *(const float4*)(lnb + col);
        __half2 h0 = __floats2half2_rn((v.x - mu) * rs * gg.x + bb.x,
                                       (v.y - mu) * rs * gg.y + bb.y);
        __half2 h1 = __floats2half2_rn((v.z - mu) * rs * gg.z + bb.z,
                                       (v.w - mu) * rs * gg.w + bb.w);
        *(uint2*)(g_xnh + (size_t)row * DD + col) =
            make_uint2(*(uint32_t*)&h0, *(uint32_t*)&h1);
    } else {
        // RoPE tables
        int idx = (bid - F2H_BLKS - LN_BLKS) * 256 + t;
        if (idx >= SS * (DD/2)) return;
        int pos = idx >> 9;
        int i   = idx & 511;
        double invf = exp(-((double)(2 * i) / (double)DD) * log(10000.0));
        float  ang  = __fmul_rn((float)pos, (float)invf);
        double r    = (double)ang;
        const double TWO_PI = 6.283185307179586476925286766559;
        r -= TWO_PI * rint(r / TWO_PI);
        float rf = (float)r;
        g_cos[idx] = cosf(rf);
        g_sin[idx] = sinf(rf);
    }
}

// ---------------- pipelined HGEMM core: BK=64, 2-stage cp.async ---------------
#define GH_ROWB   144                   // bytes per smem row (72 halfs: 64 + pad)
#define GH_TILE   (128 * GH_ROWB)       // 18432 B per operand per stage
#define GH_STAGE  (2 * GH_TILE)         // 36864
#define GH_SMEM   (2 * GH_STAGE)        // 73728

struct GemmAcc { float a[4][4][4]; };

__device__ __forceinline__ void gemm_ld_stage(const __half* __restrict__ Ab, int lda,
                                              const __half* __restrict__ Bb, int ldb,
                                              uint32_t st, int k0, int tid) {
    #pragma unroll
    for (int i = 0; i < 8; i++) {
        int c   = tid + i * 256;          // 0..2047
        int op  = c >> 10;                // 0 = A, 1 = B
        int row = (c & 1023) >> 3;        // 0..127
        int ck  = (c & 7) * 8;            // halfs 0..56
        const __half* src = (op ? Bb + (size_t)row * ldb : Ab + (size_t)row * lda) + k0 + ck;
        cp16(st + (uint32_t)(op * GH_TILE + row * GH_ROWB + ck * 2), src);
    }
}

__device__ __forceinline__ void gemm_core(const __half* __restrict__ A,
                                          const __half* __restrict__ B,
                                          int K, int lda, int ldb,
                                          int mblk, int nblk,
                                          uint32_t sbase, GemmAcc& AC) {
    int tid = threadIdx.x, warp = tid >> 5, lane = tid & 31;
    int wm = (warp & 1) * 64;
    int wn = (warp >> 1) * 32;

    const __half* Ab = A + (size_t)(mblk * 128) * lda;
    const __half* Bb = B + (size_t)(nblk * 128) * ldb;

    uint32_t aOff[4], bOff[4];
    #pragma unroll
    for (int mt = 0; mt < 4; mt++)
        aOff[mt] = (uint32_t)((wm + mt * 16 + (lane & 15)) * GH_ROWB + (lane >> 4) * 16);
    #pragma unroll
    for (int nt = 0; nt < 4; nt++)
        bOff[nt] = (uint32_t)((wn + nt * 8 + (lane & 7)) * GH_ROWB + ((lane >> 3) & 1) * 16)
                 + GH_TILE;

    #pragma unroll
    for (int mt = 0; mt < 4; mt++)
        #pragma unroll
        for (int nt = 0; nt < 4; nt++)
            #pragma unroll
            for (int r = 0; r < 4; r++) AC.a[mt][nt][r] = 0.f;

    int nk = K >> 6;

    gemm_ld_stage(Ab, lda, Bb, ldb, sbase, 0, tid);
    cp_commit();
    cp_wait<0>();
    __syncthreads();

    for (int it = 0; it < nk; it++) {
        if (it + 1 < nk) {
            gemm_ld_stage(Ab, lda, Bb, ldb,
                          sbase + ((it + 1) & 1) * GH_STAGE, (it + 1) << 6, tid);
            cp_commit();
        }

        uint32_t sa = sbase + (it & 1) * GH_STAGE;
        #pragma unroll
        for (int ks = 0; ks < 4; ks++) {
            uint32_t af[4][4], bf[4][2];
            #pragma unroll
            for (int mt = 0; mt < 4; mt++) LDSM4(af[mt], sa + aOff[mt] + ks * 32);
            #pragma unroll
            for (int nt = 0; nt < 4; nt++) LDSM2(bf[nt], sa + bOff[nt] + ks * 32);
            #pragma unroll
            for (int mt = 0; mt < 4; mt++)
                #pragma unroll
                for (int nt = 0; nt < 4; nt++)
                    mma_fp16(AC.a[mt][nt], af[mt], bf[nt]);
        }

        if (it + 1 < nk) {
            cp_wait<0>();
            __syncthreads();
        }
    }
}

// ---- QKV GEMM with fused bias + RoPE epilogue -> fp16 g_qkvh -----------------
__global__ void __launch_bounds__(256, 2)
gemm_qkv_rope(const float* __restrict__ bias) {
    extern __shared__ __align__(16) char gsm[];
    GemmAcc AC;
    gemm_core(g_xnh, g_wqkvh, DD, DD, DD, blockIdx.y, blockIdx.x, smem_u32(gsm), AC);
    int tid = threadIdx.x, warp = tid >> 5, lane = tid & 31;
    int g = lane >> 2, t4 = lane & 3;
    int wm = (warp & 1) * 64, wn = (warp >> 1) * 32;
    int sec = blockIdx.x >> 3;          // 0=q, 1=k, 2=v
    #pragma unroll
    for (int mt = 0; mt < 4; mt++) {
        int row = blockIdx.y * 128 + wm + mt * 16 + g;
        #pragma unroll
        for (int nt = 0; nt < 4; nt++) {
            int col = blockIdx.x * 128 + wn + nt * 8 + 2 * t4;
            float b0 = bias[col], b1 = bias[col + 1];
            float o0 = AC.a[mt][nt][0] + b0, o1 = AC.a[mt][nt][1] + b1;
            float o2 = AC.a[mt][nt][2] + b0, o3 = AC.a[mt][nt][3] + b1;
            if (sec < 2) {
                int i  = (col & 1023) >> 1;
                int p0 = row & (SS - 1);
                int p1 = (row + 8) & (SS - 1);
                float c0 = g_cos[p0 * 512 + i], s0 = g_sin[p0 * 512 + i];
                float c1 = g_cos[p1 * 512 + i], s1 = g_sin[p1 * 512 + i];
                float r0 = o0 * c0 - o1 * s0, r1 = o1 * c0 + o0 * s0;
                float r2 = o2 * c1 - o3 * s1, r3 = o3 * c1 + o2 * s1;
                o0 = r0; o1 = r1; o2 = r2; o3 = r3;
            }
            *(uint32_t*)&g_qkvh[(size_t)row * D3 + col]       = pack_h2(o0, o1);
            *(uint32_t*)&g_qkvh[(size_t)(row + 8) * D3 + col] = pack_h2(o2, o3);
        }
    }
}

// ---- merged in-projections: q,k,v -> fp16 ------------------------------------
__global__ void __launch_bounds__(256, 2)
gemm_inproj(const float* __restrict__ bias_all) {
    extern __shared__ __align__(16) char gsm[];
    int sec = blockIdx.x >> 3, nb = blockIdx.x & 7;
    const __half* A = g_qkvh + sec * DD;
    const __half* B = g_winh + (size_t)sec * DD * DD;
    GemmAcc AC;
    gemm_core(A, B, DD, D3, DD, blockIdx.y, nb, smem_u32(gsm), AC);
    const float* bias = bias_all + sec * DD;
    __half* Chi = (sec == 0) ? g_q_hi : (sec == 1) ? g_k_hi : g_v_hi;
    int tid = threadIdx.x, warp = tid >> 5, lane = tid & 31;
    int g = lane >> 2, t4 = lane & 3;
    int wm = (warp & 1) * 64, wn = (warp >> 1) * 32;
    #pragma unroll
    for (int mt = 0; mt < 4; mt++) {
        int row = blockIdx.y * 128 + wm + mt * 16 + g;
        #pragma unroll
        for (int nt = 0; nt < 4; nt++) {
            int col = nb * 128 + wn + nt * 8 + 2 * t4;
            float b0 = bias[col], b1 = bias[col + 1];
            float e0 = AC.a[mt][nt][0] + b0, e1 = AC.a[mt][nt][1] + b1;
            float e2 = AC.a[mt][nt][2] + b0, e3 = AC.a[mt][nt][3] + b1;
            *(uint32_t*)&Chi[(size_t)row * DD + col]       = pack_h2(e0, e1);
            *(uint32_t*)&Chi[(size_t)(row + 8) * DD + col] = pack_h2(e2, e3);
        }
    }
}

// ---- out-projection: fp32 epilogue -------------------------------------------
__global__ void __launch_bounds__(256, 2)
gemm_out(const float* __restrict__ bias, float* __restrict__ C) {
    extern __shared__ __align__(16) char gsm[];
    GemmAcc AC;
    gemm_core(g_atth, g_wouth, DD, DD, DD, blockIdx.y, blockIdx.x, smem_u32(gsm), AC);
    int tid = threadIdx.x, warp = tid >> 5, lane = tid & 31;
    int g = lane >> 2, t4 = lane & 3;
    int wm = (warp & 1) * 64, wn = (warp >> 1) * 32;
    #pragma unroll
    for (int mt = 0; mt < 4; mt++) {
        int row = blockIdx.y * 128 + wm + mt * 16 + g;
        #pragma unroll
        for (int nt = 0; nt < 4; nt++) {
            int col = blockIdx.x * 128 + wn + nt * 8 + 2 * t4;
            float b0 = bias[col], b1 = bias[col + 1];
            float2 o0 = make_float2(AC.a[mt][nt][0] + b0, AC.a[mt][nt][1] + b1);
            float2 o1 = make_float2(AC.a[mt][nt][2] + b0, AC.a[mt][nt][3] + b1);
            *(float2*)&C[(size_t)row * DD + col]       = o0;
            *(float2*)&C[(size_t)(row + 8) * DD + col] = o1;
        }
    }
}

// ---------------- Tensor-core flash attention ---------------------------------
// S = Qhi*Khi ; fp32 softmax ; O = P*Vhi.   64 mma per KV-iter.
#define AROW   72
#define AQ_HI  0
#define AKV0   (128*AROW)                // 9216 halfs
#define AKV_ST (2*64*AROW)               // 9216 halfs per stage (khi, vhi)
#define V_HI_O (64*AROW)
#define ATT_SMEM ((AKV0 + 2*AKV_ST) * 2) // 55296 bytes

__global__ void __launch_bounds__(256, 2) attn_kernel(const float* __restrict__ mask) {
    extern __shared__ __align__(16) __half asm_[];
    uint32_t sb = smem_u32(asm_);
    int q0 = blockIdx.x * 128;
    int h  = blockIdx.y;
    int b  = blockIdx.z;
    int tid = threadIdx.x, warp = tid >> 5, lane = tid & 31;
    int g = lane >> 2, t4 = lane & 3;

    const __half* qhig = g_q_hi + ((size_t)(b * SS + q0)) * DD + h * HD;
    const __half* khig = g_k_hi + ((size_t)b * SS) * DD + h * HD;
    const __half* vhig = g_v_hi + ((size_t)b * SS) * DD + h * HD;
    const float* mrow0 = mask + ((size_t)(b * SS + q0 + warp * 16 + g)) * SS;
    const float* mrow1 = mrow0 + 8 * SS;

    // stage Q hi (128 x 64)
    {
        #pragma unroll
        for (int i = 0; i < 4; i++) {
            int c = tid + i * 256;
            int row = c >> 3, ck = (c & 7) * 8;
            cp16(sb + (uint32_t)(AQ_HI + row * AROW + ck) * 2, qhig + (size_t)row * DD + ck);
        }
        cp_commit();
    }
    // prologue: KV tile 0 (khi, vhi): 1024 chunks
    {
        #pragma unroll
        for (int i = 0; i < 4; i++) {
            int c = tid + i * 256;
            int mat = c >> 9, row = (c & 511) >> 3, ck = (c & 7) * 8;
            const __half* src = (mat == 0 ? khig : vhig) + (size_t)row * DD + ck;
            cp16(sb + (uint32_t)(AKV0 + mat * 64 * AROW + row * AROW + ck) * 2, src);
        }
        cp_commit();
    }

    cp_wait<0>();
    __syncthreads();

    uint32_t qhi[4][4];
    uint32_t qbase = sb + (uint32_t)((warp * 16 + (lane & 15)) * AROW * 2 + (lane >> 4) * 16);
    #pragma unroll
    for (int ks = 0; ks < 4; ks++) LDSM4(qhi[ks], qbase + ks * 32);

    float m0 = -1e30f, m1 = -1e30f, l0 = 0.f, l1 = 0.f;
    float oacc[8][4];
    #pragma unroll
    for (int nt = 0; nt < 8; nt++)
        #pragma unroll
        for (int r = 0; r < 4; r++) oacc[nt][r] = 0.f;

    for (int it = 0; it < SS / 64; it++) {
        if (it + 1 < SS / 64) {
            int j1 = (it + 1) * 64;
            uint32_t st = (uint32_t)(AKV0 + ((it + 1) & 1) * AKV_ST);
            #pragma unroll
            for (int i = 0; i < 4; i++) {
                int c = tid + i * 256;
                int mat = c >> 9, row = (c & 511) >> 3, ck = (c & 7) * 8;
                const __half* src = (mat == 0 ? khig : vhig) + (size_t)(j1 + row) * DD + ck;
                cp16(sb + (st + (uint32_t)(mat * 64 * AROW + row * AROW + ck)) * 2, src);
            }
            cp_commit();
        }

        int j0 = it * 64;
        uint32_t stb = sb + (uint32_t)(AKV0 + (it & 1) * AKV_ST) * 2;
        uint32_t kfb = stb + (uint32_t)((lane & 7) * AROW * 2 + ((lane >> 3) & 1) * 16);
        uint32_t vfb = stb + V_HI_O * 2 + (uint32_t)((lane & 15) * AROW * 2);

        // S = Qhi * Khi
        float sacc[8][4];
        #pragma unroll
        for (int nt = 0; nt < 8; nt++)
            #pragma unroll
            for (int r = 0; r < 4; r++) sacc[nt][r] = 0.f;

        #pragma unroll
        for (int ks = 0; ks < 4; ks++) {
            #pragma unroll
            for (int nt = 0; nt < 8; nt++) {
                uint32_t khi[2];
                LDSM2(khi, kfb + (uint32_t)(nt * 8 * AROW * 2) + ks * 32);
                mma_fp16(sacc[nt], qhi[ks], khi);
            }
        }

        const float scl = 0.125f;
        #pragma unroll
        for (int nt = 0; nt < 8; nt++) {
            int col = j0 + nt * 8 + 2 * t4;
            float2 mk0 = *(const float2*)&mrow0[col];
            float2 mk1 = *(const float2*)&mrow1[col];
            sacc[nt][0] = sacc[nt][0] * scl + mk0.x;
            sacc[nt][1] = sacc[nt][1] * scl + mk0.y;
            sacc[nt][2] = sacc[nt][2] * scl + mk1.x;
            sacc[nt][3] = sacc[nt][3] * scl + mk1.y;
        }

        float rx0 = -1e30f, rx1 = -1e30f;
        #pragma unroll
        for (int nt = 0; nt < 8; nt++) {
            rx0 = fmaxf(rx0, fmaxf(sacc[nt][0], sacc[nt][1]));
            rx1 = fmaxf(rx1, fmaxf(sacc[nt][2], sacc[nt][3]));
        }
        rx0 = fmaxf(rx0, __shfl_xor_sync(0xffffffffu, rx0, 1));
        rx0 = fmaxf(rx0, __shfl_xor_sync(0xffffffffu, rx0, 2));
        rx1 = fmaxf(rx1, __shfl_xor_sync(0xffffffffu, rx1, 1));
        rx1 = fmaxf(rx1, __shfl_xor_sync(0xffffffffu, rx1, 2));
        float mn0 = fmaxf(m0, rx0), mn1 = fmaxf(m1, rx1);
        float rs0 = 0.f, rs1 = 0.f;
        #pragma unroll
        for (int nt = 0; nt < 8; nt++) {
            sacc[nt][0] = __expf(sacc[nt][0] - mn0);
            sacc[nt][1] = __expf(sacc[nt][1] - mn0);
            sacc[nt][2] = __expf(sacc[nt][2] - mn1);
            sacc[nt][3] = __expf(sacc[nt][3] - mn1);
            rs0 += sacc[nt][0] + sacc[nt][1];
            rs1 += sacc[nt][2] + sacc[nt][3];
        }
        rs0 += __shfl_xor_sync(0xffffffffu, rs0, 1);
        rs0 += __shfl_xor_sync(0xffffffffu, rs0, 2);
        rs1 += __shfl_xor_sync(0xffffffffu, rs1, 1);
        rs1 += __shfl_xor_sync(0xffffffffu, rs1, 2);
        float c0 = __expf(m0 - mn0), c1 = __expf(m1 - mn1);
        l0 = l0 * c0 + rs0;  m0 = mn0;
        l1 = l1 * c1 + rs1;  m1 = mn1;
        #pragma unroll
        for (int nt = 0; nt < 8; nt++) {
            oacc[nt][0] *= c0; oacc[nt][1] *= c0;
            oacc[nt][2] *= c1; oacc[nt][3] *= c1;
        }

        // O += P * Vhi
        #pragma unroll
        for (int kk = 0; kk < 4; kk++) {
            uint32_t pa[4];
            pa[0] = pack_h2(sacc[2*kk  ][0], sacc[2*kk  ][1]);
            pa[1] = pack_h2(sacc[2*kk  ][2], sacc[2*kk  ][3]);
            pa[2] = pack_h2(sacc[2*kk+1][0], sacc[2*kk+1][1]);
            pa[3] = pack_h2(sacc[2*kk+1][2], sacc[2*kk+1][3]);
            #pragma unroll
            for (int nt = 0; nt < 8; nt++) {
                uint32_t vhi[2];
                LDSM2T(vhi, vfb + (uint32_t)(kk * 16 * AROW * 2) + nt * 16);
                mma_fp16(oacc[nt], pa, vhi);
            }
        }

        if (it + 1 < SS / 64) {
            cp_wait<0>();
            __syncthreads();
        }
    }

    float inv0 = 1.0f / l0, inv1 = 1.0f / l1;
    __half* ob = g_atth + ((size_t)(b * SS + q0 + warp * 16)) * DD + h * HD;
    #pragma unroll
    for (int nt = 0; nt < 8; nt++) {
        int col = nt * 8 + 2 * t4;
        __half2 h0 = __floats2half2_rn(oacc[nt][0] * inv0, oacc[nt][1] * inv0);
        __half2 h1 = __floats2half2_rn(oacc[nt][2] * inv1, oacc[nt][3] * inv1);
        *(uint32_t*)&ob[(size_t)g * DD + col]       = *(uint32_t*)&h0;
        *(uint32_t*)&ob[(size_t)(g + 8) * DD + col] = *(uint32_t*)&h1;
    }
}

// ---------------- launch ------------------------------------------------------
extern "C" void kernel_launch(void* const* d_in, const int* in_sizes, int n_in,
                              void* d_out, int out_size) {
    const float* x     = (const float*)d_in[0];
    const float* mask  = (const float*)d_in[1];
    const float* ln_g  = (const float*)d_in[2];
    const float* ln_b  = (const float*)d_in[3];
    const float* w_qkv = (const float*)d_in[4];
    const float* b_qkv = (const float*)d_in[5];
    const float* in_w  = (const float*)d_in[6];
    const float* in_b  = (const float*)d_in[7];
    const float* out_w = (const float*)d_in[8];
    const float* out_b = (const float*)d_in[9];

    cudaFuncSetAttribute(attn_kernel,
                         cudaFuncAttributeMaxDynamicSharedMemorySize, ATT_SMEM);
    cudaFuncSetAttribute(gemm_qkv_rope,
                         cudaFuncAttributeMaxDynamicSharedMemorySize, GH_SMEM);
    cudaFuncSetAttribute(gemm_inproj,
                         cudaFuncAttributeMaxDynamicSharedMemorySize, GH_SMEM);
    cudaFuncSetAttribute(gemm_out,
                         cudaFuncAttributeMaxDynamicSharedMemorySize, GH_SMEM);

    // 0. merged prep: weight f2h + LayerNorm + RoPE tables
    prep_kernel<<<F2H_BLKS + LN_BLKS + RT_BLKS, 256>>>(x, ln_g, ln_b,
                                                       w_qkv, in_w, out_w);
    // 1. fused QKV projection + bias + RoPE -> fp16 g_qkvh
    gemm_qkv_rope<<<dim3(D3/128, BS/128), 256, GH_SMEM>>>(b_qkv);
    // 2. merged in-projections -> fp16
    gemm_inproj<<<dim3(D3/128, BS/128), 256, GH_SMEM>>>(in_b);
    // 3. tensor-core flash attention -> fp16
    attn_kernel<<<dim3(SS/128, HH, BB), 256, ATT_SMEM>>>(mask);
    // 4. out-projection -> d_out (fp32)
    gemm_out<<<dim3(DD/128, BS/128), 256, GH_SMEM>>>(out_b, (float*)d_out);
}